// round 1
// baseline (speedup 1.0000x reference)
#include <cuda_runtime.h>
#include <math.h>

#define B_  32768
#define D_  768
#define H_  1024
#define L_  256
#define M_  32

// Scratch (allocation-free): two ping-pong activation buffers sized for the
// widest layer (B x 2H) plus the latent buffer.
__device__ float g_bufA[(size_t)B_ * 2 * H_];
__device__ float g_bufB[(size_t)B_ * 2 * H_];
__device__ float g_z[(size_t)B_ * L_];

// ---------------------------------------------------------------------------
// SGEMM: C[M,N] = A[M,K] @ W[N,K]^T + bias  (optional leaky-relu epilogue)
// 128x128 tile, BK=16, 256 threads, 8x8 per thread, double-buffered smem.
// Assumes M%128==0, N%128==0, K%16==0 (true for all layers here).
// ---------------------------------------------------------------------------
#define BM 128
#define BN 128
#define BKK 16
#define PAD 4

template<int ACT>
__global__ __launch_bounds__(256)
void gemm_bias_kernel(const float* __restrict__ A, const float* __restrict__ W,
                      const float* __restrict__ bias, float* __restrict__ C,
                      int N, int K) {
    __shared__ float As[2][BKK][BM + PAD];
    __shared__ float Ws[2][BKK][BN + PAD];

    const int tid     = threadIdx.x;
    const int rowBase = blockIdx.y * BM;
    const int colBase = blockIdx.x * BN;

    const int tRow = (tid >> 4) * 8;   // 0..120
    const int tCol = (tid & 15) * 8;   // 0..120

    const int lr0 = tid >> 2;          // 0..63
    const int lk  = (tid & 3) * 4;     // 0,4,8,12

    const float* Ag = A + (size_t)rowBase * K;
    const float* Wg = W + (size_t)colBase * K;

    float acc[8][8];
    #pragma unroll
    for (int i = 0; i < 8; i++)
        #pragma unroll
        for (int j = 0; j < 8; j++) acc[i][j] = 0.f;

    const int ktiles = K / BKK;

    float4 a0, a1, w0, w1;
    // prologue: load tile 0
    a0 = *(const float4*)(Ag + (size_t)lr0        * K + lk);
    a1 = *(const float4*)(Ag + (size_t)(lr0 + 64) * K + lk);
    w0 = *(const float4*)(Wg + (size_t)lr0        * K + lk);
    w1 = *(const float4*)(Wg + (size_t)(lr0 + 64) * K + lk);

#define STORE_TILE(buf)                                                        \
    do {                                                                       \
        As[buf][lk + 0][lr0] = a0.x;  As[buf][lk + 1][lr0] = a0.y;             \
        As[buf][lk + 2][lr0] = a0.z;  As[buf][lk + 3][lr0] = a0.w;             \
        As[buf][lk + 0][lr0 + 64] = a1.x; As[buf][lk + 1][lr0 + 64] = a1.y;    \
        As[buf][lk + 2][lr0 + 64] = a1.z; As[buf][lk + 3][lr0 + 64] = a1.w;    \
        Ws[buf][lk + 0][lr0] = w0.x;  Ws[buf][lk + 1][lr0] = w0.y;             \
        Ws[buf][lk + 2][lr0] = w0.z;  Ws[buf][lk + 3][lr0] = w0.w;             \
        Ws[buf][lk + 0][lr0 + 64] = w1.x; Ws[buf][lk + 1][lr0 + 64] = w1.y;    \
        Ws[buf][lk + 2][lr0 + 64] = w1.z; Ws[buf][lk + 3][lr0 + 64] = w1.w;    \
    } while (0)

    STORE_TILE(0);
    __syncthreads();

    for (int kt = 0; kt < ktiles; kt++) {
        const int cur = kt & 1;
        if (kt + 1 < ktiles) {
            const int ko = (kt + 1) * BKK + lk;
            a0 = *(const float4*)(Ag + (size_t)lr0        * K + ko);
            a1 = *(const float4*)(Ag + (size_t)(lr0 + 64) * K + ko);
            w0 = *(const float4*)(Wg + (size_t)lr0        * K + ko);
            w1 = *(const float4*)(Wg + (size_t)(lr0 + 64) * K + ko);
        }

        #pragma unroll
        for (int kk = 0; kk < BKK; kk++) {
            float rA[8], rB[8];
            *(float4*)&rA[0] = *(const float4*)&As[cur][kk][tRow];
            *(float4*)&rA[4] = *(const float4*)&As[cur][kk][tRow + 4];
            *(float4*)&rB[0] = *(const float4*)&Ws[cur][kk][tCol];
            *(float4*)&rB[4] = *(const float4*)&Ws[cur][kk][tCol + 4];
            #pragma unroll
            for (int i = 0; i < 8; i++)
                #pragma unroll
                for (int j = 0; j < 8; j++)
                    acc[i][j] = fmaf(rA[i], rB[j], acc[i][j]);
        }

        if (kt + 1 < ktiles) STORE_TILE(cur ^ 1);
        __syncthreads();
    }
#undef STORE_TILE

    float bv[8];
    #pragma unroll
    for (int j = 0; j < 8; j++) bv[j] = bias[colBase + tCol + j];

    #pragma unroll
    for (int i = 0; i < 8; i++) {
        float* crow = C + (size_t)(rowBase + tRow + i) * N + colBase + tCol;
        float4 o0, o1;
        float v;
        v = acc[i][0] + bv[0]; if (ACT) v = v >= 0.f ? v : 0.2f * v; o0.x = v;
        v = acc[i][1] + bv[1]; if (ACT) v = v >= 0.f ? v : 0.2f * v; o0.y = v;
        v = acc[i][2] + bv[2]; if (ACT) v = v >= 0.f ? v : 0.2f * v; o0.z = v;
        v = acc[i][3] + bv[3]; if (ACT) v = v >= 0.f ? v : 0.2f * v; o0.w = v;
        v = acc[i][4] + bv[4]; if (ACT) v = v >= 0.f ? v : 0.2f * v; o1.x = v;
        v = acc[i][5] + bv[5]; if (ACT) v = v >= 0.f ? v : 0.2f * v; o1.y = v;
        v = acc[i][6] + bv[6]; if (ACT) v = v >= 0.f ? v : 0.2f * v; o1.z = v;
        v = acc[i][7] + bv[7]; if (ACT) v = v >= 0.f ? v : 0.2f * v; o1.w = v;
        *(float4*)(crow)     = o0;
        *(float4*)(crow + 4) = o1;
    }
}

// ---------------------------------------------------------------------------
// Row LayerNorm + leaky-relu, in place. One block (256 threads) per row.
// NV4=1 -> H=1024, NV4=2 -> H=2048. Two-pass (mean, then centered var).
// ---------------------------------------------------------------------------
__device__ __forceinline__ float block_reduce_sum(float val, float* red) {
    const int lane = threadIdx.x & 31;
    const int w    = threadIdx.x >> 5;
    #pragma unroll
    for (int o = 16; o; o >>= 1) val += __shfl_xor_sync(0xffffffffu, val, o);
    if (lane == 0) red[w] = val;
    __syncthreads();
    float t = (lane < 8) ? red[lane] : 0.f;
    if (w == 0) {
        #pragma unroll
        for (int o = 4; o; o >>= 1) t += __shfl_xor_sync(0xffffffffu, t, o);
        if (lane == 0) red[0] = t;
    }
    __syncthreads();
    float r = red[0];
    __syncthreads();
    return r;
}

template<int NV4>
__global__ __launch_bounds__(256)
void ln_lrelu_kernel(float* __restrict__ X, const float* __restrict__ g,
                     const float* __restrict__ b) {
    const int H = NV4 * 1024;
    const int tid = threadIdx.x;
    float* row = X + (size_t)blockIdx.x * H;
    __shared__ float red[8];

    float4 v[NV4];
    float s = 0.f;
    #pragma unroll
    for (int q = 0; q < NV4; q++) {
        v[q] = *(const float4*)(row + (tid + 256 * q) * 4);
        s += v[q].x + v[q].y + v[q].z + v[q].w;
    }
    const float mean = block_reduce_sum(s, red) * (1.f / H);

    float ss = 0.f;
    #pragma unroll
    for (int q = 0; q < NV4; q++) {
        float dx;
        dx = v[q].x - mean; ss += dx * dx;
        dx = v[q].y - mean; ss += dx * dx;
        dx = v[q].z - mean; ss += dx * dx;
        dx = v[q].w - mean; ss += dx * dx;
    }
    const float var  = block_reduce_sum(ss, red) * (1.f / H);
    const float rstd = rsqrtf(var + 1e-5f);

    #pragma unroll
    for (int q = 0; q < NV4; q++) {
        const int col = (tid + 256 * q) * 4;
        const float4 g4 = *(const float4*)(g + col);
        const float4 b4 = *(const float4*)(b + col);
        float4 o;
        float y;
        y = (v[q].x - mean) * rstd * g4.x + b4.x; o.x = y >= 0.f ? y : 0.2f * y;
        y = (v[q].y - mean) * rstd * g4.y + b4.y; o.y = y >= 0.f ? y : 0.2f * y;
        y = (v[q].z - mean) * rstd * g4.z + b4.z; o.z = y >= 0.f ? y : 0.2f * y;
        y = (v[q].w - mean) * rstd * g4.w + b4.w; o.w = y >= 0.f ? y : 0.2f * y;
        *(float4*)(row + col) = o;
    }
}

// ---------------------------------------------------------------------------
// Fused reparameterize + context-memory attention.
// z = mu + eps*exp(0.5*lv); attn = softmax(z @ ctx^T); z_enh = z + 0.1*attn@ctx
// Block = 256 threads = 8 warps, one row per warp. ctx (32x256) in smem.
// ---------------------------------------------------------------------------
__global__ __launch_bounds__(256)
void reparam_attn_kernel(const float* __restrict__ mu, const float* __restrict__ lv,
                         const float* __restrict__ eps, const float* __restrict__ ctx,
                         float* __restrict__ z_enh) {
    __shared__ float ctxs[M_][L_ + 1];
    __shared__ float zs[8][L_];
    __shared__ float attns[8][M_];

    const int tid = threadIdx.x;
    for (int i = tid; i < M_ * L_; i += 256)
        ctxs[i >> 8][i & 255] = ctx[i];
    __syncthreads();

    const int w    = tid >> 5;
    const int lane = tid & 31;
    const size_t row = (size_t)blockIdx.x * 8 + w;
    const float* murow = mu  + row * L_;
    const float* lvrow = lv  + row * L_;
    const float* eprow = eps + row * L_;

    #pragma unroll
    for (int i = 0; i < 8; i++) {
        const int j = lane + 32 * i;
        zs[w][j] = murow[j] + eprow[j] * expf(0.5f * lvrow[j]);
    }
    __syncwarp();

    // lane m computes score_m
    float s = 0.f;
    #pragma unroll 8
    for (int j = 0; j < L_; j++)
        s = fmaf(zs[w][j], ctxs[lane][j], s);

    float mx = s;
    #pragma unroll
    for (int o = 16; o; o >>= 1) mx = fmaxf(mx, __shfl_xor_sync(0xffffffffu, mx, o));
    float e = expf(s - mx);
    float tot = e;
    #pragma unroll
    for (int o = 16; o; o >>= 1) tot += __shfl_xor_sync(0xffffffffu, tot, o);
    attns[w][lane] = e / tot;
    __syncwarp();

    float* orow = z_enh + row * L_;
    #pragma unroll
    for (int i = 0; i < 8; i++) {
        const int j = lane + 32 * i;
        float add = 0.f;
        #pragma unroll
        for (int m = 0; m < M_; m++)
            add = fmaf(attns[w][m], ctxs[m][j], add);
        orow[j] = zs[w][j] + 0.1f * add;
    }
}

// ---------------------------------------------------------------------------
extern "C" void kernel_launch(void* const* d_in, const int* in_sizes, int n_in,
                              void* d_out, int out_size) {
    (void)in_sizes; (void)n_in; (void)out_size;
    const float* x      = (const float*)d_in[0];
    const float* eps    = (const float*)d_in[1];
    const float* enc_w1 = (const float*)d_in[2];
    const float* enc_b1 = (const float*)d_in[3];
    const float* ln1_g  = (const float*)d_in[4];
    const float* ln1_b  = (const float*)d_in[5];
    const float* enc_w2 = (const float*)d_in[6];
    const float* enc_b2 = (const float*)d_in[7];
    const float* ln2_g  = (const float*)d_in[8];
    const float* ln2_b  = (const float*)d_in[9];
    const float* mu_w   = (const float*)d_in[10];
    const float* mu_b   = (const float*)d_in[11];
    const float* lv_w   = (const float*)d_in[12];
    const float* lv_b   = (const float*)d_in[13];
    const float* di_w   = (const float*)d_in[14];
    const float* di_b   = (const float*)d_in[15];
    const float* dec_w1 = (const float*)d_in[16];
    const float* dec_b1 = (const float*)d_in[17];
    const float* dln1_g = (const float*)d_in[18];
    const float* dln1_b = (const float*)d_in[19];
    const float* dec_w2 = (const float*)d_in[20];
    const float* dec_b2 = (const float*)d_in[21];
    const float* dln2_g = (const float*)d_in[22];
    const float* dln2_b = (const float*)d_in[23];
    const float* dec_w3 = (const float*)d_in[24];
    const float* dec_b3 = (const float*)d_in[25];
    const float* ctx    = (const float*)d_in[26];

    float* out     = (float*)d_out;
    float* out_rec = out;
    float* out_mu  = out + (size_t)B_ * D_;
    float* out_lv  = out_mu + (size_t)B_ * L_;

    float *bufA, *bufB, *zbuf;
    cudaGetSymbolAddress((void**)&bufA, g_bufA);
    cudaGetSymbolAddress((void**)&bufB, g_bufB);
    cudaGetSymbolAddress((void**)&zbuf, g_z);

    const dim3 blk(256);
    const dim3 gH (H_ / BN,     B_ / BM);
    const dim3 gL (L_ / BN,     B_ / BM);
    const dim3 g2H(2 * H_ / BN, B_ / BM);
    const dim3 gD (D_ / BN,     B_ / BM);

    // encoder
    gemm_bias_kernel<0><<<gH, blk>>>(x, enc_w1, enc_b1, bufA, H_, D_);
    ln_lrelu_kernel<1><<<B_, blk>>>(bufA, ln1_g, ln1_b);
    gemm_bias_kernel<0><<<gH, blk>>>(bufA, enc_w2, enc_b2, bufB, H_, H_);
    ln_lrelu_kernel<1><<<B_, blk>>>(bufB, ln2_g, ln2_b);
    gemm_bias_kernel<0><<<gL, blk>>>(bufB, mu_w, mu_b, out_mu, L_, H_);
    gemm_bias_kernel<0><<<gL, blk>>>(bufB, lv_w, lv_b, out_lv, L_, H_);
    // reparameterize + context attention
    reparam_attn_kernel<<<B_ / 8, blk>>>(out_mu, out_lv, eps, ctx, zbuf);
    // decoder
    gemm_bias_kernel<1><<<gH, blk>>>(zbuf, di_w, di_b, bufA, H_, L_);
    gemm_bias_kernel<0><<<gH, blk>>>(bufA, dec_w1, dec_b1, bufB, H_, H_);
    ln_lrelu_kernel<1><<<B_, blk>>>(bufB, dln1_g, dln1_b);
    gemm_bias_kernel<0><<<g2H, blk>>>(bufB, dec_w2, dec_b2, bufA, 2 * H_, H_);
    ln_lrelu_kernel<2><<<B_, blk>>>(bufA, dln2_g, dln2_b);
    gemm_bias_kernel<0><<<gD, blk>>>(bufA, dec_w3, dec_b3, out_rec, D_, 2 * H_);
}